// round 2
// baseline (speedup 1.0000x reference)
#include <cuda_runtime.h>

#define BB 32
#define NN 4096
#define DD 64
#define KK 256

// Scratch: projections [b][j][d], j = low-rank index (0..255), d = head dim
__device__ __align__(16) float g_Kp[BB * KK * DD];
__device__ __align__(16) float g_Vp[BB * KK * DD];

// ---------------------------------------------------------------------------
// Kernel A: Kp[b][j][d] = sum_n K[b][n][d] * E[n][j]   (and same for V/F)
// grid: (KK/64, BB, 2), block: 256 threads. Each block computes a [64 j x 64 d]
// tile for one batch, looping N in chunks of 64 with double smem tiles.
// ---------------------------------------------------------------------------
__global__ void proj_kernel(const float* __restrict__ Kin,
                            const float* __restrict__ Vin,
                            const float* __restrict__ Ein,
                            const float* __restrict__ Fin) {
    const int which = blockIdx.z;
    const float* __restrict__ X = which ? Vin : Kin;   // [B][N][64]
    const float* __restrict__ W = which ? Fin : Ein;   // [N][256]
    float* __restrict__ P = which ? g_Vp : g_Kp;

    const int b  = blockIdx.y;
    const int j0 = blockIdx.x * 64;
    const int tid = threadIdx.x;
    const int tx = tid & 15;   // d group (4 cols each)
    const int ty = tid >> 4;   // j group (4 rows each)

    __shared__ float Xs[64 * 64];   // [nn][d]
    __shared__ float Ws[64 * 64];   // [nn][j-local]

    float c[4][4];
#pragma unroll
    for (int i = 0; i < 4; i++)
#pragma unroll
        for (int jx = 0; jx < 4; jx++) c[i][jx] = 0.0f;

    float4* Xs4 = (float4*)Xs;
    float4* Ws4 = (float4*)Ws;

    for (int n0 = 0; n0 < NN; n0 += 64) {
        // load X chunk: X[b][n0+nn][d], contiguous 64*64 floats
        const float4* Xg = (const float4*)(X + ((size_t)b * NN + n0) * DD);
#pragma unroll
        for (int i = 0; i < 4; i++) Xs4[tid + i * 256] = Xg[tid + i * 256];
        // load W chunk: W[n0+nn][j0 + 0..63], row stride 256 floats
        const float4* Wg = (const float4*)W;
#pragma unroll
        for (int i = 0; i < 4; i++) {
            int idx = tid + i * 256;        // f4 index into [64][16]
            int nn = idx >> 4, j4 = idx & 15;
            Ws4[idx] = Wg[(size_t)(n0 + nn) * (KK / 4) + (j0 >> 2) + j4];
        }
        __syncthreads();

#pragma unroll 8
        for (int nn = 0; nn < 64; nn++) {
            float4 a4 = Ws4[nn * 16 + ty];   // broadcast within tx-group
            float4 x4 = Xs4[nn * 16 + tx];
            float av[4] = {a4.x, a4.y, a4.z, a4.w};
            float xv[4] = {x4.x, x4.y, x4.z, x4.w};
#pragma unroll
            for (int i = 0; i < 4; i++)
#pragma unroll
                for (int jx = 0; jx < 4; jx++) c[i][jx] += av[i] * xv[jx];
        }
        __syncthreads();
    }

    float* Pb = P + (size_t)b * KK * DD;
#pragma unroll
    for (int i = 0; i < 4; i++) {
        float4 v = make_float4(c[i][0], c[i][1], c[i][2], c[i][3]);
        ((float4*)(Pb + (size_t)(j0 + ty * 4 + i) * DD))[tx] = v;
    }
}

// ---------------------------------------------------------------------------
// Kernel B: fused scores -> softmax -> PV.
// grid: (NN/(8*RPW), BB), block: 256 threads (8 warps). Block loads Kp[b] and
// Vp[b] (64 KB each) into smem with rows padded to 68 floats (conflict-free
// LDS.128 for the j-indexed reads). Each warp owns one row at a time:
//   scores: lane l holds s[jj] for j = jj*32 + l  (8 scores/lane)
//   softmax: warp shfl reductions
//   PV: lanes 0-15 handle j 0..127, lanes 16-31 handle j 128..255, each lane
//       accumulates one float4 of d; halves combined via shfl_down(16).
// ---------------------------------------------------------------------------
#define RPW 16
#define ROW_STRIDE 17   // float4 stride per j row (= 68 floats)

__global__ void attn_kernel(const float* __restrict__ Q, float* __restrict__ out) {
    extern __shared__ float sm[];
    float* Kp_s = sm;                          // 256*68 floats
    float* Vp_s = Kp_s + 256 * 68;             // 256*68 floats
    float* q_s  = Vp_s + 256 * 68;             // 8*64
    float* p_s  = q_s + 8 * 64;                // 8*256

    const int b   = blockIdx.y;
    const int tid = threadIdx.x;
    const int w   = tid >> 5;
    const int l   = tid & 31;

    // stage projections: global [256][64] -> smem [256][68]
    {
        const float4* Kg = (const float4*)(g_Kp + (size_t)b * KK * DD);
        const float4* Vg = (const float4*)(g_Vp + (size_t)b * KK * DD);
        float4* Ks4 = (float4*)Kp_s;
        float4* Vs4 = (float4*)Vp_s;
#pragma unroll
        for (int t = tid; t < 256 * 16; t += 256) {
            int j = t >> 4, i4 = t & 15;
            Ks4[j * ROW_STRIDE + i4] = Kg[t];
            Vs4[j * ROW_STRIDE + i4] = Vg[t];
        }
    }
    __syncthreads();

    const int rowBase = blockIdx.x * (8 * RPW) + w * RPW;
    const float4* Kp4 = (const float4*)Kp_s;
    const float4* Vp4 = (const float4*)Vp_s;
    float* qw = q_s + w * 64;
    float* pw = p_s + w * 256;

    for (int rr = 0; rr < RPW; rr++) {
        const int row = rowBase + rr;
        // stage q row (lanes 0-15, one float4 each)
        const float4* qg = (const float4*)(Q + ((size_t)b * NN + row) * DD);
        if (l < 16) ((float4*)qw)[l] = qg[l];
        __syncwarp();

        // ---- scores ----
        float s[8];
#pragma unroll
        for (int jj = 0; jj < 8; jj++) s[jj] = 0.0f;
#pragma unroll
        for (int i4 = 0; i4 < 16; i4++) {
            float4 q4 = ((const float4*)qw)[i4];
#pragma unroll
            for (int jj = 0; jj < 8; jj++) {
                float4 k4 = Kp4[(jj * 32 + l) * ROW_STRIDE + i4];
                s[jj] += q4.x * k4.x + q4.y * k4.y + q4.z * k4.z + q4.w * k4.w;
            }
        }

        // ---- softmax over 256 (distributed: 8/lane) ----
        float m = -1e30f;
#pragma unroll
        for (int jj = 0; jj < 8; jj++) { s[jj] *= 0.125f; m = fmaxf(m, s[jj]); }
#pragma unroll
        for (int o = 16; o > 0; o >>= 1) m = fmaxf(m, __shfl_xor_sync(0xffffffffu, m, o));
        float sum = 0.0f;
        float e[8];
#pragma unroll
        for (int jj = 0; jj < 8; jj++) { e[jj] = __expf(s[jj] - m); sum += e[jj]; }
#pragma unroll
        for (int o = 16; o > 0; o >>= 1) sum += __shfl_xor_sync(0xffffffffu, sum, o);
        const float inv = 1.0f / sum;
#pragma unroll
        for (int jj = 0; jj < 8; jj++) pw[jj * 32 + l] = e[jj] * inv;
        __syncwarp();

        // ---- PV ----
        float4 acc = make_float4(0.f, 0.f, 0.f, 0.f);
        const int d4 = l & 15;
        const int jbase = (l >> 4) * 128;
#pragma unroll 4
        for (int j = 0; j < 128; j++) {
            float pj = pw[jbase + j];
            float4 v4 = Vp4[(jbase + j) * ROW_STRIDE + d4];
            acc.x += pj * v4.x;
            acc.y += pj * v4.y;
            acc.z += pj * v4.z;
            acc.w += pj * v4.w;
        }
        acc.x += __shfl_down_sync(0xffffffffu, acc.x, 16);
        acc.y += __shfl_down_sync(0xffffffffu, acc.y, 16);
        acc.z += __shfl_down_sync(0xffffffffu, acc.z, 16);
        acc.w += __shfl_down_sync(0xffffffffu, acc.w, 16);
        if (l < 16)
            ((float4*)(out + ((size_t)b * NN + row) * DD))[l] = acc;
        __syncwarp();
    }
}

// ---------------------------------------------------------------------------
extern "C" void kernel_launch(void* const* d_in, const int* in_sizes, int n_in,
                              void* d_out, int out_size) {
    const float* Q = (const float*)d_in[0];
    const float* K = (const float*)d_in[1];
    const float* V = (const float*)d_in[2];
    const float* E = (const float*)d_in[3];
    const float* F = (const float*)d_in[4];
    float* out = (float*)d_out;

    static bool attr_set = false;
    const int smem_b = (256 * 68 * 2 + 8 * 64 + 8 * 256) * sizeof(float); // 149504 B
    if (!attr_set) {
        cudaFuncSetAttribute(attn_kernel, cudaFuncAttributeMaxDynamicSharedMemorySize, smem_b);
        attr_set = true;
    }

    proj_kernel<<<dim3(KK / 64, BB, 2), 256>>>(K, V, E, F);
    attn_kernel<<<dim3(NN / (8 * RPW), BB), 256, smem_b>>>(Q, out);
}

// round 4
// speedup vs baseline: 1.5382x; 1.5382x over previous
#include <cuda_runtime.h>

#define BB 32
#define NN 4096
#define DD 64
#define KK 256

// Scratch: projections [b][j][d], j = low-rank index (0..255), d = head dim
__device__ __align__(16) float g_Kp[BB * KK * DD];
__device__ __align__(16) float g_Vp[BB * KK * DD];

// ---------------------------------------------------------------------------
// Kernel A: Kp[b][j][d] = sum_n K[b][n][d] * E[n][j]   (and same for V/F)
// ---------------------------------------------------------------------------
__global__ void proj_kernel(const float* __restrict__ Kin,
                            const float* __restrict__ Vin,
                            const float* __restrict__ Ein,
                            const float* __restrict__ Fin) {
    const int which = blockIdx.z;
    const float* __restrict__ X = which ? Vin : Kin;   // [B][N][64]
    const float* __restrict__ W = which ? Fin : Ein;   // [N][256]
    float* __restrict__ P = which ? g_Vp : g_Kp;

    const int b  = blockIdx.y;
    const int j0 = blockIdx.x * 64;
    const int tid = threadIdx.x;
    const int tx = tid & 15;   // d group (4 cols each)
    const int ty = tid >> 4;   // j group (4 rows each)

    __shared__ float Xs[64 * 64];   // [nn][d]
    __shared__ float Ws[64 * 64];   // [nn][j-local]

    float c[4][4];
#pragma unroll
    for (int i = 0; i < 4; i++)
#pragma unroll
        for (int jx = 0; jx < 4; jx++) c[i][jx] = 0.0f;

    float4* Xs4 = (float4*)Xs;
    float4* Ws4 = (float4*)Ws;

    for (int n0 = 0; n0 < NN; n0 += 64) {
        const float4* Xg = (const float4*)(X + ((size_t)b * NN + n0) * DD);
#pragma unroll
        for (int i = 0; i < 4; i++) Xs4[tid + i * 256] = Xg[tid + i * 256];
        const float4* Wg = (const float4*)W;
#pragma unroll
        for (int i = 0; i < 4; i++) {
            int idx = tid + i * 256;        // f4 index into [64][16]
            int nn = idx >> 4, j4 = idx & 15;
            Ws4[idx] = Wg[(size_t)(n0 + nn) * (KK / 4) + (j0 >> 2) + j4];
        }
        __syncthreads();

#pragma unroll 8
        for (int nn = 0; nn < 64; nn++) {
            float4 a4 = Ws4[nn * 16 + ty];
            float4 x4 = Xs4[nn * 16 + tx];
            float av[4] = {a4.x, a4.y, a4.z, a4.w};
            float xv[4] = {x4.x, x4.y, x4.z, x4.w};
#pragma unroll
            for (int i = 0; i < 4; i++)
#pragma unroll
                for (int jx = 0; jx < 4; jx++) c[i][jx] += av[i] * xv[jx];
        }
        __syncthreads();
    }

    float* Pb = P + (size_t)b * KK * DD;
#pragma unroll
    for (int i = 0; i < 4; i++) {
        float4 v = make_float4(c[i][0], c[i][1], c[i][2], c[i][3]);
        ((float4*)(Pb + (size_t)(j0 + ty * 4 + i) * DD))[tx] = v;
    }
}

// ---------------------------------------------------------------------------
// Kernel B: fused scores -> softmax -> PV, register-blocked 4 rows per warp.
// Each Kp/Vp float4 read from smem serves 4 query rows (4x less LDS traffic).
// grid: (32, BB), block: 256 threads (8 warps). Block covers 128 rows:
//   warp w owns rows [base + w*16, +16), processed in 4 groups of 4.
// ---------------------------------------------------------------------------
#define RG 4            // rows per warp per group
#define GRP 4           // groups per block  -> 8 warps * 4 * 4 = 128 rows/block
#define ROW_STRIDE 17   // float4 stride per j row (= 68 floats, conflict-free)

__global__ void attn_kernel(const float* __restrict__ Q, float* __restrict__ out) {
    extern __shared__ float sm[];
    float* Kp_s = sm;                          // 256*68 floats
    float* Vp_s = Kp_s + 256 * 68;             // 256*68 floats
    float* q_s  = Vp_s + 256 * 68;             // [8][RG][64]
    float* p_s  = q_s + 8 * RG * 64;           // [8][RG][256]

    const int b   = blockIdx.y;
    const int tid = threadIdx.x;
    const int w   = tid >> 5;
    const int l   = tid & 31;

    // stage projections: global [256][64] -> smem [256][68]
    {
        const float4* Kg = (const float4*)(g_Kp + (size_t)b * KK * DD);
        const float4* Vg = (const float4*)(g_Vp + (size_t)b * KK * DD);
        float4* Ks4 = (float4*)Kp_s;
        float4* Vs4 = (float4*)Vp_s;
#pragma unroll
        for (int t = tid; t < 256 * 16; t += 256) {
            int j = t >> 4, i4 = t & 15;
            Ks4[j * ROW_STRIDE + i4] = Kg[t];
            Vs4[j * ROW_STRIDE + i4] = Vg[t];
        }
    }
    __syncthreads();

    const int warpRowBase = blockIdx.x * (8 * RG * GRP) + w * (RG * GRP);
    const float4* Kp4 = (const float4*)Kp_s;
    const float4* Vp4 = (const float4*)Vp_s;
    float4* qw4 = (float4*)(q_s + w * RG * 64);      // [RG][16] float4
    float* pw   = p_s + w * RG * 256;                // [RG][256]

    for (int g = 0; g < GRP; g++) {
        const int row0 = warpRowBase + g * RG;

        // stage 4 q rows: 64 float4 total, 2 per lane
        {
            const float4* qg = (const float4*)(Q + ((size_t)b * NN + row0) * DD);
#pragma unroll
            for (int t = l; t < RG * 16; t += 32) qw4[t] = qg[t];
        }
        __syncwarp();

        // ---- scores: s[r][jj], j = jj*32 + l ----
        float s[RG][8];
#pragma unroll
        for (int r = 0; r < RG; r++)
#pragma unroll
            for (int jj = 0; jj < 8; jj++) s[r][jj] = 0.0f;

#pragma unroll
        for (int i4 = 0; i4 < 16; i4++) {
            float4 q0 = qw4[0 * 16 + i4];
            float4 q1 = qw4[1 * 16 + i4];
            float4 q2 = qw4[2 * 16 + i4];
            float4 q3 = qw4[3 * 16 + i4];
#pragma unroll
            for (int jj = 0; jj < 8; jj++) {
                float4 k4 = Kp4[(jj * 32 + l) * ROW_STRIDE + i4];
                s[0][jj] += q0.x * k4.x + q0.y * k4.y + q0.z * k4.z + q0.w * k4.w;
                s[1][jj] += q1.x * k4.x + q1.y * k4.y + q1.z * k4.z + q1.w * k4.w;
                s[2][jj] += q2.x * k4.x + q2.y * k4.y + q2.z * k4.z + q2.w * k4.w;
                s[3][jj] += q3.x * k4.x + q3.y * k4.y + q3.z * k4.z + q3.w * k4.w;
            }
        }

        // ---- softmax (unnormalized exp to smem; 1/sum applied after PV) ----
        float inv[RG];
#pragma unroll
        for (int r = 0; r < RG; r++) {
            float m = -1e30f;
#pragma unroll
            for (int jj = 0; jj < 8; jj++) { s[r][jj] *= 0.125f; m = fmaxf(m, s[r][jj]); }
#pragma unroll
            for (int o = 16; o > 0; o >>= 1) m = fmaxf(m, __shfl_xor_sync(0xffffffffu, m, o));
            float sum = 0.0f;
#pragma unroll
            for (int jj = 0; jj < 8; jj++) {
                float e = __expf(s[r][jj] - m);
                sum += e;
                pw[r * 256 + jj * 32 + l] = e;
            }
#pragma unroll
            for (int o = 16; o > 0; o >>= 1) sum += __shfl_xor_sync(0xffffffffu, sum, o);
            inv[r] = 1.0f / sum;
        }
        __syncwarp();

        // ---- PV: lanes 0-15 -> j 0..127, lanes 16-31 -> j 128..255 ----
        float4 acc[RG];
#pragma unroll
        for (int r = 0; r < RG; r++) acc[r] = make_float4(0.f, 0.f, 0.f, 0.f);
        const int d4 = l & 15;
        const int jb = (l >> 4) * 128;
#pragma unroll 4
        for (int j = 0; j < 128; j++) {
            float4 v4 = Vp4[(jb + j) * ROW_STRIDE + d4];
#pragma unroll
            for (int r = 0; r < RG; r++) {
                float pj = pw[r * 256 + jb + j];   // broadcast LDS
                acc[r].x += pj * v4.x;
                acc[r].y += pj * v4.y;
                acc[r].z += pj * v4.z;
                acc[r].w += pj * v4.w;
            }
        }

#pragma unroll
        for (int r = 0; r < RG; r++) {
            acc[r].x += __shfl_down_sync(0xffffffffu, acc[r].x, 16);
            acc[r].y += __shfl_down_sync(0xffffffffu, acc[r].y, 16);
            acc[r].z += __shfl_down_sync(0xffffffffu, acc[r].z, 16);
            acc[r].w += __shfl_down_sync(0xffffffffu, acc[r].w, 16);
            if (l < 16) {
                float4 o4 = make_float4(acc[r].x * inv[r], acc[r].y * inv[r],
                                        acc[r].z * inv[r], acc[r].w * inv[r]);
                ((float4*)(out + ((size_t)b * NN + row0 + r) * DD))[l] = o4;
            }
        }
        __syncwarp();
    }
}

// ---------------------------------------------------------------------------
extern "C" void kernel_launch(void* const* d_in, const int* in_sizes, int n_in,
                              void* d_out, int out_size) {
    const float* Q = (const float*)d_in[0];
    const float* K = (const float*)d_in[1];
    const float* V = (const float*)d_in[2];
    const float* E = (const float*)d_in[3];
    const float* F = (const float*)d_in[4];
    float* out = (float*)d_out;

    static bool attr_set = false;
    const int smem_b = (256 * 68 * 2 + 8 * RG * 64 + 8 * RG * 256) * sizeof(float); // 180224 B
    if (!attr_set) {
        cudaFuncSetAttribute(attn_kernel, cudaFuncAttributeMaxDynamicSharedMemorySize, smem_b);
        attr_set = true;
    }

    proj_kernel<<<dim3(KK / 64, BB, 2), 256>>>(K, V, E, F);
    attn_kernel<<<dim3(NN / (8 * RG * GRP), BB), 256, smem_b>>>(Q, out);
}

// round 7
// speedup vs baseline: 1.7711x; 1.1514x over previous
#include <cuda_runtime.h>
#include <cstdint>

#define BB 32
#define NN 4096
#define DD 64
#define KK 256

// Scratch: projections [b][j][d]
__device__ __align__(16) float g_Kp[BB * KK * DD];
__device__ __align__(16) float g_Vp[BB * KK * DD];

__device__ __forceinline__ float tf32_rna(float x) {
    uint32_t u;
    asm("cvt.rna.tf32.f32 %0, %1;" : "=r"(u) : "f"(x));
    return __uint_as_float(u);
}

// mma.sync m16n8k8 tf32: D += A*B, A row-major 16x8, B col-major 8x8, fp32 acc
__device__ __forceinline__ void mma_tf32(float c[4], const float a[4], const float b[2]) {
    asm volatile(
        "mma.sync.aligned.m16n8k8.row.col.f32.tf32.tf32.f32 "
        "{%0, %1, %2, %3}, {%4, %5, %6, %7}, {%8, %9}, {%0, %1, %2, %3};"
        : "+f"(c[0]), "+f"(c[1]), "+f"(c[2]), "+f"(c[3])
        : "r"(__float_as_uint(a[0])), "r"(__float_as_uint(a[1])),
          "r"(__float_as_uint(a[2])), "r"(__float_as_uint(a[3])),
          "r"(__float_as_uint(b[0])), "r"(__float_as_uint(b[1])));
}

// ---------------------------------------------------------------------------
// Kernel A: proj via mma.sync tf32 (3xTF32 hi/lo compensated).
//   C[j, d] = sum_n W[n][j] * X[b][n][d]
// grid (2 jh, 32 b, 2 which), 256 threads (8 warps).
// Block tile: [128 j x 64 d]; warp tile [32 j x 32 d] (warp grid 4j x 2d).
// K chunked by 32; operands staged hi/lo into smem with row stride 36 floats
// (fragment LDS banks = (4r + c) % 32 -> conflict-free; STS.128 conflict-free).
// ---------------------------------------------------------------------------
#define KC  32
#define AST 36

__global__ void __launch_bounds__(256, 1)
proj_mma_kernel(const float* __restrict__ Kin, const float* __restrict__ Vin,
                const float* __restrict__ Ein, const float* __restrict__ Fin) {
    extern __shared__ float psm[];
    float* Ah = psm;                 // [128][36]
    float* Al = Ah + 128 * AST;
    float* Bh = Al + 128 * AST;      // [64][36]
    float* Bl = Bh + 64 * AST;

    const int jh    = blockIdx.x;
    const int b     = blockIdx.y;
    const int which = blockIdx.z;
    const float* __restrict__ X = which ? Vin : Kin;   // [B][N][64]
    const float* __restrict__ W = which ? Fin : Ein;   // [N][256]
    float* __restrict__ P = which ? g_Vp : g_Kp;
    const int j0 = jh * 128;

    const int tid = threadIdx.x;
    const int wid = tid >> 5;
    const int l   = tid & 31;
    const int wj  = wid & 3;     // j quarter (32 rows)
    const int wd  = wid >> 2;    // d half (32 cols)

    // staging maps
    const int jA = tid & 127, gA = tid >> 7;   // A: 128 j-lanes, 2 n-groups of 16
    const int dB = tid & 63,  gB = tid >> 6;   // B: 64 d-lanes, 4 n-groups of 8

    float c[2][4][4];
#pragma unroll
    for (int mt = 0; mt < 2; mt++)
#pragma unroll
        for (int nt = 0; nt < 4; nt++)
#pragma unroll
            for (int r = 0; r < 4; r++) c[mt][nt][r] = 0.0f;

    for (int n0 = 0; n0 < NN; n0 += KC) {
        // ---- stage A = E^T slice: A[j][n] = W[n0+n][j0+j], hi/lo ----
#pragma unroll
        for (int grp = 0; grp < 4; grp++) {
            const int n = gA * 16 + grp * 4;
            const float* Wp = W + (size_t)(n0 + n) * KK + j0 + jA;
            float x0 = Wp[0], x1 = Wp[KK], x2 = Wp[2 * KK], x3 = Wp[3 * KK];
            float h0 = tf32_rna(x0), h1 = tf32_rna(x1), h2 = tf32_rna(x2), h3 = tf32_rna(x3);
            *(float4*)(Ah + jA * AST + n) = make_float4(h0, h1, h2, h3);
            *(float4*)(Al + jA * AST + n) = make_float4(
                tf32_rna(x0 - h0), tf32_rna(x1 - h1), tf32_rna(x2 - h2), tf32_rna(x3 - h3));
        }
        // ---- stage B = X^T slice: B[d][n] = X[b][n0+n][d], hi/lo ----
#pragma unroll
        for (int grp = 0; grp < 2; grp++) {
            const int n = gB * 8 + grp * 4;
            const float* Xp = X + ((size_t)b * NN + n0 + n) * DD + dB;
            float x0 = Xp[0], x1 = Xp[DD], x2 = Xp[2 * DD], x3 = Xp[3 * DD];
            float h0 = tf32_rna(x0), h1 = tf32_rna(x1), h2 = tf32_rna(x2), h3 = tf32_rna(x3);
            *(float4*)(Bh + dB * AST + n) = make_float4(h0, h1, h2, h3);
            *(float4*)(Bl + dB * AST + n) = make_float4(
                tf32_rna(x0 - h0), tf32_rna(x1 - h1), tf32_rna(x2 - h2), tf32_rna(x3 - h3));
        }
        __syncthreads();

        // ---- 4 K-steps of 8 ----
#pragma unroll
        for (int ks = 0; ks < 4; ks++) {
            const int kb = ks * 8 + (l & 3);
            const int ar = (l >> 2);

            float ah[2][4], al[2][4];
#pragma unroll
            for (int mt = 0; mt < 2; mt++) {
                const int row = wj * 32 + mt * 16 + ar;
                ah[mt][0] = Ah[row * AST + kb];
                ah[mt][1] = Ah[(row + 8) * AST + kb];
                ah[mt][2] = Ah[row * AST + kb + 4];
                ah[mt][3] = Ah[(row + 8) * AST + kb + 4];
                al[mt][0] = Al[row * AST + kb];
                al[mt][1] = Al[(row + 8) * AST + kb];
                al[mt][2] = Al[row * AST + kb + 4];
                al[mt][3] = Al[(row + 8) * AST + kb + 4];
            }
            float bh[4][2], bl[4][2];
#pragma unroll
            for (int nt = 0; nt < 4; nt++) {
                const int d0 = wd * 32 + nt * 8 + ar;
                bh[nt][0] = Bh[d0 * AST + kb];
                bh[nt][1] = Bh[d0 * AST + kb + 4];
                bl[nt][0] = Bl[d0 * AST + kb];
                bl[nt][1] = Bl[d0 * AST + kb + 4];
            }
#pragma unroll
            for (int mt = 0; mt < 2; mt++)
#pragma unroll
                for (int nt = 0; nt < 4; nt++) {
                    mma_tf32(c[mt][nt], ah[mt], bh[nt]);
                    mma_tf32(c[mt][nt], ah[mt], bl[nt]);
                    mma_tf32(c[mt][nt], al[mt], bh[nt]);
                }
        }
        __syncthreads();
    }

    // ---- epilogue: C[mt][nt] fragments -> P[b][j][d] ----
#pragma unroll
    for (int mt = 0; mt < 2; mt++) {
        const int row = j0 + wj * 32 + mt * 16 + (l >> 2);
        float* p = P + ((size_t)b * KK + row) * DD;
#pragma unroll
        for (int nt = 0; nt < 4; nt++) {
            const int col = wd * 32 + nt * 8 + (l & 3) * 2;
            *(float2*)(p + col)          = make_float2(c[mt][nt][0], c[mt][nt][1]);
            *(float2*)(p + 8 * DD + col) = make_float2(c[mt][nt][2], c[mt][nt][3]);
        }
    }
}

// ---------------------------------------------------------------------------
// Kernel B: fused scores -> softmax -> PV, register-blocked 8 rows per warp.
// ---------------------------------------------------------------------------
#define RG 8            // rows per warp per group
#define GRP 2           // groups per block  -> 8 warps * 8 * 2 = 128 rows/block
#define ROW_STRIDE 17   // float4 stride per j row (= 68 floats, conflict-free)

__global__ void __launch_bounds__(256, 1)
attn_kernel(const float* __restrict__ Q, float* __restrict__ out) {
    extern __shared__ float sm[];
    float* Kp_s = sm;                          // 256*68 floats
    float* Vp_s = Kp_s + 256 * 68;             // 256*68 floats
    float* q_s  = Vp_s + 256 * 68;             // [8][RG][64]
    float* p_s  = q_s + 8 * RG * 64;           // [8][RG][256]

    const int b   = blockIdx.y;
    const int tid = threadIdx.x;
    const int w   = tid >> 5;
    const int l   = tid & 31;

    // stage projections: global [256][64] -> smem [256][68]
    {
        const float4* Kg = (const float4*)(g_Kp + (size_t)b * KK * DD);
        const float4* Vg = (const float4*)(g_Vp + (size_t)b * KK * DD);
        float4* Ks4 = (float4*)Kp_s;
        float4* Vs4 = (float4*)Vp_s;
#pragma unroll
        for (int t = tid; t < 256 * 16; t += 256) {
            int j = t >> 4, i4 = t & 15;
            Ks4[j * ROW_STRIDE + i4] = Kg[t];
            Vs4[j * ROW_STRIDE + i4] = Vg[t];
        }
    }
    __syncthreads();

    const int warpRowBase = blockIdx.x * (8 * RG * GRP) + w * (RG * GRP);
    const float4* Kp4 = (const float4*)Kp_s;
    const float4* Vp4 = (const float4*)Vp_s;
    float4* qw4 = (float4*)(q_s + w * RG * 64);      // [RG][16] float4
    float* pw   = p_s + w * RG * 256;                // [RG][256]

    for (int g = 0; g < GRP; g++) {
        const int row0 = warpRowBase + g * RG;

        // stage RG q rows
        {
            const float4* qg = (const float4*)(Q + ((size_t)b * NN + row0) * DD);
#pragma unroll
            for (int t = l; t < RG * 16; t += 32) qw4[t] = qg[t];
        }
        __syncwarp();

        // ---- scores: s[r][jj], j = jj*32 + l ----
        float s[RG][8];
#pragma unroll
        for (int r = 0; r < RG; r++)
#pragma unroll
            for (int jj = 0; jj < 8; jj++) s[r][jj] = 0.0f;

#pragma unroll
        for (int i4 = 0; i4 < 16; i4++) {
            float4 q[RG];
#pragma unroll
            for (int r = 0; r < RG; r++) q[r] = qw4[r * 16 + i4];
#pragma unroll
            for (int jj = 0; jj < 8; jj++) {
                float4 k4 = Kp4[(jj * 32 + l) * ROW_STRIDE + i4];
#pragma unroll
                for (int r = 0; r < RG; r++) {
                    s[r][jj] += q[r].x * k4.x + q[r].y * k4.y +
                                q[r].z * k4.z + q[r].w * k4.w;
                }
            }
        }

        // ---- softmax (unnormalized exp to smem; 1/sum folded into epilogue) ----
        float inv[RG];
#pragma unroll
        for (int r = 0; r < RG; r++) {
            float m = -1e30f;
#pragma unroll
            for (int jj = 0; jj < 8; jj++) { s[r][jj] *= 0.125f; m = fmaxf(m, s[r][jj]); }
#pragma unroll
            for (int o = 16; o > 0; o >>= 1) m = fmaxf(m, __shfl_xor_sync(0xffffffffu, m, o));
            float sum = 0.0f;
#pragma unroll
            for (int jj = 0; jj < 8; jj++) {
                float e = __expf(s[r][jj] - m);
                sum += e;
                pw[r * 256 + jj * 32 + l] = e;
            }
#pragma unroll
            for (int o = 16; o > 0; o >>= 1) sum += __shfl_xor_sync(0xffffffffu, sum, o);
            inv[r] = 1.0f / sum;
        }
        __syncwarp();

        // ---- PV: lanes 0-15 -> j 0..127, lanes 16-31 -> j 128..255 ----
        float4 acc[RG];
#pragma unroll
        for (int r = 0; r < RG; r++) acc[r] = make_float4(0.f, 0.f, 0.f, 0.f);
        const int d4 = l & 15;
        const int jb = (l >> 4) * 128;
#pragma unroll 4
        for (int j = 0; j < 128; j++) {
            float4 v4 = Vp4[(jb + j) * ROW_STRIDE + d4];
#pragma unroll
            for (int r = 0; r < RG; r++) {
                float pj = pw[r * 256 + jb + j];   // broadcast LDS
                acc[r].x += pj * v4.x;
                acc[r].y += pj * v4.y;
                acc[r].z += pj * v4.z;
                acc[r].w += pj * v4.w;
            }
        }

#pragma unroll
        for (int r = 0; r < RG; r++) {
            acc[r].x += __shfl_down_sync(0xffffffffu, acc[r].x, 16);
            acc[r].y += __shfl_down_sync(0xffffffffu, acc[r].y, 16);
            acc[r].z += __shfl_down_sync(0xffffffffu, acc[r].z, 16);
            acc[r].w += __shfl_down_sync(0xffffffffu, acc[r].w, 16);
            if (l < 16) {
                float4 o4 = make_float4(acc[r].x * inv[r], acc[r].y * inv[r],
                                        acc[r].z * inv[r], acc[r].w * inv[r]);
                ((float4*)(out + ((size_t)b * NN + row0 + r) * DD))[l] = o4;
            }
        }
        __syncwarp();
    }
}

// ---------------------------------------------------------------------------
extern "C" void kernel_launch(void* const* d_in, const int* in_sizes, int n_in,
                              void* d_out, int out_size) {
    const float* Q = (const float*)d_in[0];
    const float* K = (const float*)d_in[1];
    const float* V = (const float*)d_in[2];
    const float* E = (const float*)d_in[3];
    const float* F = (const float*)d_in[4];
    float* out = (float*)d_out;

    static bool attr_set = false;
    const int attn_smem = (256 * 68 * 2 + 8 * RG * 64 + 8 * RG * 256) * sizeof(float); // 221184
    const int proj_smem = (2 * 128 * AST + 2 * 64 * AST) * sizeof(float);              // 55296
    if (!attr_set) {
        cudaFuncSetAttribute(attn_kernel, cudaFuncAttributeMaxDynamicSharedMemorySize, attn_smem);
        cudaFuncSetAttribute(proj_mma_kernel, cudaFuncAttributeMaxDynamicSharedMemorySize, proj_smem);
        attr_set = true;
    }

    proj_mma_kernel<<<dim3(2, BB, 2), 256, proj_smem>>>(K, V, E, F);
    attn_kernel<<<dim3(NN / (8 * RG * GRP), BB), 256, attn_smem>>>(Q, out);
}

// round 8
// speedup vs baseline: 1.9960x; 1.1269x over previous
#include <cuda_runtime.h>
#include <cstdint>

#define BB 32
#define NN 4096
#define DD 64
#define KK 256

// Scratch: projections [b][j][d]
__device__ __align__(16) float g_Kp[BB * KK * DD];
__device__ __align__(16) float g_Vp[BB * KK * DD];

__device__ __forceinline__ float tf32_rna(float x) {
    uint32_t u;
    asm("cvt.rna.tf32.f32 %0, %1;" : "=r"(u) : "f"(x));
    return __uint_as_float(u);
}

// mma.sync m16n8k8 tf32: D += A*B, A row-major 16x8, B col-major 8x8, fp32 acc
__device__ __forceinline__ void mma_tf32(float c[4], const float a[4], const float b[2]) {
    asm volatile(
        "mma.sync.aligned.m16n8k8.row.col.f32.tf32.tf32.f32 "
        "{%0, %1, %2, %3}, {%4, %5, %6, %7}, {%8, %9}, {%0, %1, %2, %3};"
        : "+f"(c[0]), "+f"(c[1]), "+f"(c[2]), "+f"(c[3])
        : "r"(__float_as_uint(a[0])), "r"(__float_as_uint(a[1])),
          "r"(__float_as_uint(a[2])), "r"(__float_as_uint(a[3])),
          "r"(__float_as_uint(b[0])), "r"(__float_as_uint(b[1])));
}

// ---------------------------------------------------------------------------
// Kernel A: proj via mma.sync tf32 (3xTF32 hi/lo compensated), software
// pipelined: global loads for chunk c+1 issue in registers while the MMA loop
// for chunk c runs, ping-ponged over two register sets.
//   C[j, d] = sum_n W[n][j] * X[b][n][d]
// grid (2 jh, 32 b, 2 which), 256 threads (8 warps).
// Block tile [128 j x 64 d]; warp tile [32 j x 32 d]; K chunked by 32.
// ---------------------------------------------------------------------------
#define KC  32
#define AST 36
#define PNCH (NN / KC)

__global__ void __launch_bounds__(256, 1)
proj_mma_kernel(const float* __restrict__ Kin, const float* __restrict__ Vin,
                const float* __restrict__ Ein, const float* __restrict__ Fin) {
    extern __shared__ float psm[];
    float* Ah = psm;                 // [128][36]
    float* Al = Ah + 128 * AST;
    float* Bh = Al + 128 * AST;      // [64][36]
    float* Bl = Bh + 64 * AST;

    const int jh    = blockIdx.x;
    const int b     = blockIdx.y;
    const int which = blockIdx.z;
    const float* __restrict__ X = which ? Vin : Kin;   // [B][N][64]
    const float* __restrict__ W = which ? Fin : Ein;   // [N][256]
    float* __restrict__ P = which ? g_Vp : g_Kp;
    const int j0 = jh * 128;

    const int tid = threadIdx.x;
    const int wid = tid >> 5;
    const int l   = tid & 31;
    const int wj  = wid & 3;     // j quarter (32 rows)
    const int wd  = wid >> 2;    // d half (32 cols)

    // staging maps
    const int jA = tid & 127, gA = tid >> 7;   // A: 128 j-lanes, 2 n-groups of 16
    const int dB = tid & 63,  gB = tid >> 6;   // B: 64 d-lanes, 4 n-groups of 8

    float c[2][4][4];
#pragma unroll
    for (int mt = 0; mt < 2; mt++)
#pragma unroll
        for (int nt = 0; nt < 4; nt++)
#pragma unroll
            for (int r = 0; r < 4; r++) c[mt][nt][r] = 0.0f;

    // ---- pipeline helpers ----
    auto loadA = [&](float* r, int cc) {
#pragma unroll
        for (int grp = 0; grp < 4; grp++) {
            const int n = gA * 16 + grp * 4;
            const float* Wp = W + (size_t)(cc * KC + n) * KK + j0 + jA;
            r[grp * 4 + 0] = Wp[0];
            r[grp * 4 + 1] = Wp[KK];
            r[grp * 4 + 2] = Wp[2 * KK];
            r[grp * 4 + 3] = Wp[3 * KK];
        }
    };
    auto loadB = [&](float* r, int cc) {
#pragma unroll
        for (int grp = 0; grp < 2; grp++) {
            const int n = gB * 8 + grp * 4;
            const float* Xp = X + ((size_t)b * NN + cc * KC + n) * DD + dB;
            r[grp * 4 + 0] = Xp[0];
            r[grp * 4 + 1] = Xp[DD];
            r[grp * 4 + 2] = Xp[2 * DD];
            r[grp * 4 + 3] = Xp[3 * DD];
        }
    };
    auto stage = [&](const float* ra, const float* rb) {
#pragma unroll
        for (int grp = 0; grp < 4; grp++) {
            const int n = gA * 16 + grp * 4;
            float x0 = ra[grp * 4], x1 = ra[grp * 4 + 1],
                  x2 = ra[grp * 4 + 2], x3 = ra[grp * 4 + 3];
            float h0 = tf32_rna(x0), h1 = tf32_rna(x1),
                  h2 = tf32_rna(x2), h3 = tf32_rna(x3);
            *(float4*)(Ah + jA * AST + n) = make_float4(h0, h1, h2, h3);
            *(float4*)(Al + jA * AST + n) = make_float4(
                tf32_rna(x0 - h0), tf32_rna(x1 - h1),
                tf32_rna(x2 - h2), tf32_rna(x3 - h3));
        }
#pragma unroll
        for (int grp = 0; grp < 2; grp++) {
            const int n = gB * 8 + grp * 4;
            float x0 = rb[grp * 4], x1 = rb[grp * 4 + 1],
                  x2 = rb[grp * 4 + 2], x3 = rb[grp * 4 + 3];
            float h0 = tf32_rna(x0), h1 = tf32_rna(x1),
                  h2 = tf32_rna(x2), h3 = tf32_rna(x3);
            *(float4*)(Bh + dB * AST + n) = make_float4(h0, h1, h2, h3);
            *(float4*)(Bl + dB * AST + n) = make_float4(
                tf32_rna(x0 - h0), tf32_rna(x1 - h1),
                tf32_rna(x2 - h2), tf32_rna(x3 - h3));
        }
    };
    auto mmaChunk = [&]() {
#pragma unroll
        for (int ks = 0; ks < 4; ks++) {
            const int kb = ks * 8 + (l & 3);
            const int ar = (l >> 2);

            float ah[2][4], al[2][4];
#pragma unroll
            for (int mt = 0; mt < 2; mt++) {
                const int row = wj * 32 + mt * 16 + ar;
                ah[mt][0] = Ah[row * AST + kb];
                ah[mt][1] = Ah[(row + 8) * AST + kb];
                ah[mt][2] = Ah[row * AST + kb + 4];
                ah[mt][3] = Ah[(row + 8) * AST + kb + 4];
                al[mt][0] = Al[row * AST + kb];
                al[mt][1] = Al[(row + 8) * AST + kb];
                al[mt][2] = Al[row * AST + kb + 4];
                al[mt][3] = Al[(row + 8) * AST + kb + 4];
            }
            float bh[4][2], bl[4][2];
#pragma unroll
            for (int nt = 0; nt < 4; nt++) {
                const int d0 = wd * 32 + nt * 8 + ar;
                bh[nt][0] = Bh[d0 * AST + kb];
                bh[nt][1] = Bh[d0 * AST + kb + 4];
                bl[nt][0] = Bl[d0 * AST + kb];
                bl[nt][1] = Bl[d0 * AST + kb + 4];
            }
#pragma unroll
            for (int mt = 0; mt < 2; mt++)
#pragma unroll
                for (int nt = 0; nt < 4; nt++) {
                    mma_tf32(c[mt][nt], ah[mt], bh[nt]);
                    mma_tf32(c[mt][nt], ah[mt], bl[nt]);
                    mma_tf32(c[mt][nt], al[mt], bh[nt]);
                }
        }
    };

    // ---- pipelined main loop (PNCH = 128, even) ----
    float rA0[16], rB0[8], rA1[16], rB1[8];
    loadA(rA0, 0);
    loadB(rB0, 0);

    for (int cc = 0; cc < PNCH; cc += 2) {
        stage(rA0, rB0);
        __syncthreads();
        if (cc + 1 < PNCH) { loadA(rA1, cc + 1); loadB(rB1, cc + 1); }
        mmaChunk();
        __syncthreads();

        stage(rA1, rB1);
        __syncthreads();
        if (cc + 2 < PNCH) { loadA(rA0, cc + 2); loadB(rB0, cc + 2); }
        mmaChunk();
        __syncthreads();
    }

    // ---- epilogue: C fragments -> P[b][j][d] ----
#pragma unroll
    for (int mt = 0; mt < 2; mt++) {
        const int row = j0 + wj * 32 + mt * 16 + (l >> 2);
        float* p = P + ((size_t)b * KK + row) * DD;
#pragma unroll
        for (int nt = 0; nt < 4; nt++) {
            const int col = wd * 32 + nt * 8 + (l & 3) * 2;
            *(float2*)(p + col)          = make_float2(c[mt][nt][0], c[mt][nt][1]);
            *(float2*)(p + 8 * DD + col) = make_float2(c[mt][nt][2], c[mt][nt][3]);
        }
    }
}

// ---------------------------------------------------------------------------
// Kernel B: fused scores -> softmax -> PV, register-blocked 8 rows per warp.
// (unchanged from R7 passing version)
// ---------------------------------------------------------------------------
#define RG 8
#define GRP 2
#define ROW_STRIDE 17

__global__ void __launch_bounds__(256, 1)
attn_kernel(const float* __restrict__ Q, float* __restrict__ out) {
    extern __shared__ float sm[];
    float* Kp_s = sm;
    float* Vp_s = Kp_s + 256 * 68;
    float* q_s  = Vp_s + 256 * 68;
    float* p_s  = q_s + 8 * RG * 64;

    const int b   = blockIdx.y;
    const int tid = threadIdx.x;
    const int w   = tid >> 5;
    const int l   = tid & 31;

    {
        const float4* Kg = (const float4*)(g_Kp + (size_t)b * KK * DD);
        const float4* Vg = (const float4*)(g_Vp + (size_t)b * KK * DD);
        float4* Ks4 = (float4*)Kp_s;
        float4* Vs4 = (float4*)Vp_s;
#pragma unroll
        for (int t = tid; t < 256 * 16; t += 256) {
            int j = t >> 4, i4 = t & 15;
            Ks4[j * ROW_STRIDE + i4] = Kg[t];
            Vs4[j * ROW_STRIDE + i4] = Vg[t];
        }
    }
    __syncthreads();

    const int warpRowBase = blockIdx.x * (8 * RG * GRP) + w * (RG * GRP);
    const float4* Kp4 = (const float4*)Kp_s;
    const float4* Vp4 = (const float4*)Vp_s;
    float4* qw4 = (float4*)(q_s + w * RG * 64);
    float* pw   = p_s + w * RG * 256;

    for (int g = 0; g < GRP; g++) {
        const int row0 = warpRowBase + g * RG;

        {
            const float4* qg = (const float4*)(Q + ((size_t)b * NN + row0) * DD);
#pragma unroll
            for (int t = l; t < RG * 16; t += 32) qw4[t] = qg[t];
        }
        __syncwarp();

        float s[RG][8];
#pragma unroll
        for (int r = 0; r < RG; r++)
#pragma unroll
            for (int jj = 0; jj < 8; jj++) s[r][jj] = 0.0f;

#pragma unroll
        for (int i4 = 0; i4 < 16; i4++) {
            float4 q[RG];
#pragma unroll
            for (int r = 0; r < RG; r++) q[r] = qw4[r * 16 + i4];
#pragma unroll
            for (int jj = 0; jj < 8; jj++) {
                float4 k4 = Kp4[(jj * 32 + l) * ROW_STRIDE + i4];
#pragma unroll
                for (int r = 0; r < RG; r++) {
                    s[r][jj] += q[r].x * k4.x + q[r].y * k4.y +
                                q[r].z * k4.z + q[r].w * k4.w;
                }
            }
        }

        float inv[RG];
#pragma unroll
        for (int r = 0; r < RG; r++) {
            float m = -1e30f;
#pragma unroll
            for (int jj = 0; jj < 8; jj++) { s[r][jj] *= 0.125f; m = fmaxf(m, s[r][jj]); }
#pragma unroll
            for (int o = 16; o > 0; o >>= 1) m = fmaxf(m, __shfl_xor_sync(0xffffffffu, m, o));
            float sum = 0.0f;
#pragma unroll
            for (int jj = 0; jj < 8; jj++) {
                float e = __expf(s[r][jj] - m);
                sum += e;
                pw[r * 256 + jj * 32 + l] = e;
            }
#pragma unroll
            for (int o = 16; o > 0; o >>= 1) sum += __shfl_xor_sync(0xffffffffu, sum, o);
            inv[r] = 1.0f / sum;
        }
        __syncwarp();

        float4 acc[RG];
#pragma unroll
        for (int r = 0; r < RG; r++) acc[r] = make_float4(0.f, 0.f, 0.f, 0.f);
        const int d4 = l & 15;
        const int jb = (l >> 4) * 128;
#pragma unroll 4
        for (int j = 0; j < 128; j++) {
            float4 v4 = Vp4[(jb + j) * ROW_STRIDE + d4];
#pragma unroll
            for (int r = 0; r < RG; r++) {
                float pj = pw[r * 256 + jb + j];
                acc[r].x += pj * v4.x;
                acc[r].y += pj * v4.y;
                acc[r].z += pj * v4.z;
                acc[r].w += pj * v4.w;
            }
        }

#pragma unroll
        for (int r = 0; r < RG; r++) {
            acc[r].x += __shfl_down_sync(0xffffffffu, acc[r].x, 16);
            acc[r].y += __shfl_down_sync(0xffffffffu, acc[r].y, 16);
            acc[r].z += __shfl_down_sync(0xffffffffu, acc[r].z, 16);
            acc[r].w += __shfl_down_sync(0xffffffffu, acc[r].w, 16);
            if (l < 16) {
                float4 o4 = make_float4(acc[r].x * inv[r], acc[r].y * inv[r],
                                        acc[r].z * inv[r], acc[r].w * inv[r]);
                ((float4*)(out + ((size_t)b * NN + row0 + r) * DD))[l] = o4;
            }
        }
        __syncwarp();
    }
}

// ---------------------------------------------------------------------------
extern "C" void kernel_launch(void* const* d_in, const int* in_sizes, int n_in,
                              void* d_out, int out_size) {
    const float* Q = (const float*)d_in[0];
    const float* K = (const float*)d_in[1];
    const float* V = (const float*)d_in[2];
    const float* E = (const float*)d_in[3];
    const float* F = (const float*)d_in[4];
    float* out = (float*)d_out;

    static bool attr_set = false;
    const int attn_smem = (256 * 68 * 2 + 8 * RG * 64 + 8 * RG * 256) * sizeof(float); // 221184
    const int proj_smem = (2 * 128 * AST + 2 * 64 * AST) * sizeof(float);              // 55296
    if (!attr_set) {
        cudaFuncSetAttribute(attn_kernel, cudaFuncAttributeMaxDynamicSharedMemorySize, attn_smem);
        cudaFuncSetAttribute(proj_mma_kernel, cudaFuncAttributeMaxDynamicSharedMemorySize, proj_smem);
        attr_set = true;
    }

    proj_mma_kernel<<<dim3(2, BB, 2), 256, proj_smem>>>(K, V, E, F);
    attn_kernel<<<dim3(NN / (8 * RG * GRP), BB), 256, attn_smem>>>(Q, out);
}

// round 9
// speedup vs baseline: 1.9975x; 1.0008x over previous
#include <cuda_runtime.h>
#include <cuda_bf16.h>
#include <cstdint>

#define BB 32
#define NN 4096
#define DD 64
#define KK 256

// Scratch: projections [b][j][d]
__device__ __align__(16) float g_Kp[BB * KK * DD];
__device__ __align__(16) float g_Vp[BB * KK * DD];

__device__ __forceinline__ float tf32_rna(float x) {
    uint32_t u;
    asm("cvt.rna.tf32.f32 %0, %1;" : "=r"(u) : "f"(x));
    return __uint_as_float(u);
}

// mma.sync m16n8k8 tf32: D += A*B
__device__ __forceinline__ void mma_tf32(float c[4], const float a[4], const float b[2]) {
    asm volatile(
        "mma.sync.aligned.m16n8k8.row.col.f32.tf32.tf32.f32 "
        "{%0, %1, %2, %3}, {%4, %5, %6, %7}, {%8, %9}, {%0, %1, %2, %3};"
        : "+f"(c[0]), "+f"(c[1]), "+f"(c[2]), "+f"(c[3])
        : "r"(__float_as_uint(a[0])), "r"(__float_as_uint(a[1])),
          "r"(__float_as_uint(a[2])), "r"(__float_as_uint(a[3])),
          "r"(__float_as_uint(b[0])), "r"(__float_as_uint(b[1])));
}

// mma.sync m16n8k16 bf16: D += A*B (a,b are packed bf16x2 regs)
__device__ __forceinline__ void mma_bf16(float c[4], uint32_t a0, uint32_t a1,
                                         uint32_t a2, uint32_t a3,
                                         uint32_t b0, uint32_t b1) {
    asm volatile(
        "mma.sync.aligned.m16n8k16.row.col.f32.bf16.bf16.f32 "
        "{%0, %1, %2, %3}, {%4, %5, %6, %7}, {%8, %9}, {%0, %1, %2, %3};"
        : "+f"(c[0]), "+f"(c[1]), "+f"(c[2]), "+f"(c[3])
        : "r"(a0), "r"(a1), "r"(a2), "r"(a3), "r"(b0), "r"(b1));
}

// pack two floats to bf16x2: lo -> bits[15:0], hi -> bits[31:16]
__device__ __forceinline__ uint32_t pack_bf16x2(float lo, float hi) {
    uint32_t r;
    asm("cvt.rn.bf16x2.f32 %0, %1, %2;" : "=r"(r) : "f"(hi), "f"(lo));
    return r;
}
__device__ __forceinline__ float bf16lo_f(uint32_t p) { return __uint_as_float(p << 16); }
__device__ __forceinline__ float bf16hi_f(uint32_t p) { return __uint_as_float(p & 0xffff0000u); }

// split (x0,x1) into hi/lo bf16x2 pairs
__device__ __forceinline__ void split2(float x0, float x1, uint32_t& h, uint32_t& lo) {
    h  = pack_bf16x2(x0, x1);
    lo = pack_bf16x2(x0 - bf16lo_f(h), x1 - bf16hi_f(h));
}

// ---------------------------------------------------------------------------
// Kernel A: proj via mma.sync tf32 (3xTF32), software pipelined. (R8, passing)
// ---------------------------------------------------------------------------
#define KC  32
#define AST 36
#define PNCH (NN / KC)

__global__ void __launch_bounds__(256, 1)
proj_mma_kernel(const float* __restrict__ Kin, const float* __restrict__ Vin,
                const float* __restrict__ Ein, const float* __restrict__ Fin) {
    extern __shared__ float psm[];
    float* Ah = psm;
    float* Al = Ah + 128 * AST;
    float* Bh = Al + 128 * AST;
    float* Bl = Bh + 64 * AST;

    const int jh    = blockIdx.x;
    const int b     = blockIdx.y;
    const int which = blockIdx.z;
    const float* __restrict__ X = which ? Vin : Kin;
    const float* __restrict__ W = which ? Fin : Ein;
    float* __restrict__ P = which ? g_Vp : g_Kp;
    const int j0 = jh * 128;

    const int tid = threadIdx.x;
    const int wid = tid >> 5;
    const int l   = tid & 31;
    const int wj  = wid & 3;
    const int wd  = wid >> 2;

    const int jA = tid & 127, gA = tid >> 7;
    const int dB = tid & 63,  gB = tid >> 6;

    float c[2][4][4];
#pragma unroll
    for (int mt = 0; mt < 2; mt++)
#pragma unroll
        for (int nt = 0; nt < 4; nt++)
#pragma unroll
            for (int r = 0; r < 4; r++) c[mt][nt][r] = 0.0f;

    auto loadA = [&](float* r, int cc) {
#pragma unroll
        for (int grp = 0; grp < 4; grp++) {
            const int n = gA * 16 + grp * 4;
            const float* Wp = W + (size_t)(cc * KC + n) * KK + j0 + jA;
            r[grp * 4 + 0] = Wp[0];
            r[grp * 4 + 1] = Wp[KK];
            r[grp * 4 + 2] = Wp[2 * KK];
            r[grp * 4 + 3] = Wp[3 * KK];
        }
    };
    auto loadB = [&](float* r, int cc) {
#pragma unroll
        for (int grp = 0; grp < 2; grp++) {
            const int n = gB * 8 + grp * 4;
            const float* Xp = X + ((size_t)b * NN + cc * KC + n) * DD + dB;
            r[grp * 4 + 0] = Xp[0];
            r[grp * 4 + 1] = Xp[DD];
            r[grp * 4 + 2] = Xp[2 * DD];
            r[grp * 4 + 3] = Xp[3 * DD];
        }
    };
    auto stage = [&](const float* ra, const float* rb) {
#pragma unroll
        for (int grp = 0; grp < 4; grp++) {
            const int n = gA * 16 + grp * 4;
            float x0 = ra[grp * 4], x1 = ra[grp * 4 + 1],
                  x2 = ra[grp * 4 + 2], x3 = ra[grp * 4 + 3];
            float h0 = tf32_rna(x0), h1 = tf32_rna(x1),
                  h2 = tf32_rna(x2), h3 = tf32_rna(x3);
            *(float4*)(Ah + jA * AST + n) = make_float4(h0, h1, h2, h3);
            *(float4*)(Al + jA * AST + n) = make_float4(
                tf32_rna(x0 - h0), tf32_rna(x1 - h1),
                tf32_rna(x2 - h2), tf32_rna(x3 - h3));
        }
#pragma unroll
        for (int grp = 0; grp < 2; grp++) {
            const int n = gB * 8 + grp * 4;
            float x0 = rb[grp * 4], x1 = rb[grp * 4 + 1],
                  x2 = rb[grp * 4 + 2], x3 = rb[grp * 4 + 3];
            float h0 = tf32_rna(x0), h1 = tf32_rna(x1),
                  h2 = tf32_rna(x2), h3 = tf32_rna(x3);
            *(float4*)(Bh + dB * AST + n) = make_float4(h0, h1, h2, h3);
            *(float4*)(Bl + dB * AST + n) = make_float4(
                tf32_rna(x0 - h0), tf32_rna(x1 - h1),
                tf32_rna(x2 - h2), tf32_rna(x3 - h3));
        }
    };
    auto mmaChunk = [&]() {
#pragma unroll
        for (int ks = 0; ks < 4; ks++) {
            const int kb = ks * 8 + (l & 3);
            const int ar = (l >> 2);

            float ah[2][4], al[2][4];
#pragma unroll
            for (int mt = 0; mt < 2; mt++) {
                const int row = wj * 32 + mt * 16 + ar;
                ah[mt][0] = Ah[row * AST + kb];
                ah[mt][1] = Ah[(row + 8) * AST + kb];
                ah[mt][2] = Ah[row * AST + kb + 4];
                ah[mt][3] = Ah[(row + 8) * AST + kb + 4];
                al[mt][0] = Al[row * AST + kb];
                al[mt][1] = Al[(row + 8) * AST + kb];
                al[mt][2] = Al[row * AST + kb + 4];
                al[mt][3] = Al[(row + 8) * AST + kb + 4];
            }
            float bh[4][2], bl[4][2];
#pragma unroll
            for (int nt = 0; nt < 4; nt++) {
                const int d0 = wd * 32 + nt * 8 + ar;
                bh[nt][0] = Bh[d0 * AST + kb];
                bh[nt][1] = Bh[d0 * AST + kb + 4];
                bl[nt][0] = Bl[d0 * AST + kb];
                bl[nt][1] = Bl[d0 * AST + kb + 4];
            }
#pragma unroll
            for (int mt = 0; mt < 2; mt++)
#pragma unroll
                for (int nt = 0; nt < 4; nt++) {
                    mma_tf32(c[mt][nt], ah[mt], bh[nt]);
                    mma_tf32(c[mt][nt], ah[mt], bl[nt]);
                    mma_tf32(c[mt][nt], al[mt], bh[nt]);
                }
        }
    };

    float rA0[16], rB0[8], rA1[16], rB1[8];
    loadA(rA0, 0);
    loadB(rB0, 0);

    for (int cc = 0; cc < PNCH; cc += 2) {
        stage(rA0, rB0);
        __syncthreads();
        if (cc + 1 < PNCH) { loadA(rA1, cc + 1); loadB(rB1, cc + 1); }
        mmaChunk();
        __syncthreads();

        stage(rA1, rB1);
        __syncthreads();
        if (cc + 2 < PNCH) { loadA(rA0, cc + 2); loadB(rB0, cc + 2); }
        mmaChunk();
        __syncthreads();
    }

#pragma unroll
    for (int mt = 0; mt < 2; mt++) {
        const int row = j0 + wj * 32 + mt * 16 + (l >> 2);
        float* p = P + ((size_t)b * KK + row) * DD;
#pragma unroll
        for (int nt = 0; nt < 4; nt++) {
            const int col = wd * 32 + nt * 8 + (l & 3) * 2;
            *(float2*)(p + col)          = make_float2(c[mt][nt][0], c[mt][nt][1]);
            *(float2*)(p + 8 * DD + col) = make_float2(c[mt][nt][2], c[mt][nt][3]);
        }
    }
}

// ---------------------------------------------------------------------------
// Kernel B (NEW): fully tensorized flash-style attention, bf16x3 mma.sync.
// Block = 1 batch x 128 Q rows, 8 warps, each warp owns 16 rows.
// Phase 1: S = Q*Kp^T via m16n8k16 (warp tile 16x256, accum 128 regs).
// Softmax: quad shfl reductions (row lives in 4 lanes), exp in regs.
// Phase 2: O = P*Vp, P fragments come straight from the score C-fragments
//          (bf16 hi/lo split in registers) — no smem roundtrip, no syncs.
// Smem word strides: Kp/Q rows 36 words, VpT rows 132 words (both = 4 mod 32
// -> conflict-free fragment loads).
// ---------------------------------------------------------------------------
#define KP_W 36    // words per Kp/Q row (72 bf16)
#define VT_W 132   // words per VpT row (264 bf16)

// smem word offsets
#define OFF_KPH 0
#define OFF_KPL (OFF_KPH + 256 * KP_W)
#define OFF_VTH (OFF_KPL + 256 * KP_W)
#define OFF_VTL (OFF_VTH + 64 * VT_W)
#define OFF_QH  (OFF_VTL + 64 * VT_W)
#define OFF_QL  (OFF_QH + 128 * KP_W)
#define ATTN_WORDS (OFF_QL + 128 * KP_W)

__global__ void __launch_bounds__(256, 1)
attn_kernel(const float* __restrict__ Q, float* __restrict__ out) {
    extern __shared__ uint32_t asm_w[];
    uint32_t* KPH = asm_w + OFF_KPH;
    uint32_t* KPL = asm_w + OFF_KPL;
    uint32_t* VTH = asm_w + OFF_VTH;
    uint32_t* VTL = asm_w + OFF_VTL;
    uint32_t* QH  = asm_w + OFF_QH;
    uint32_t* QL  = asm_w + OFF_QL;

    const int b   = blockIdx.y;
    const int tid = threadIdx.x;
    const int w   = tid >> 5;
    const int l   = tid & 31;
    const int g   = l >> 2;
    const int q4  = l & 3;

    // ---- stage Kp: [256 j][64 d] fp32 -> bf16 hi/lo pairs along d ----
    {
        const float4* Kg = (const float4*)(g_Kp + (size_t)b * KK * DD);
        const int c16 = tid & 15;
#pragma unroll
        for (int it = 0; it < 16; it++) {
            const int j = it * 16 + (tid >> 4);
            float4 v = Kg[j * 16 + c16];
            uint32_t h01, l01, h23, l23;
            split2(v.x, v.y, h01, l01);
            split2(v.z, v.w, h23, l23);
            uint32_t* dh = KPH + j * KP_W + c16 * 2;
            uint32_t* dl = KPL + j * KP_W + c16 * 2;
            dh[0] = h01; dh[1] = h23;
            dl[0] = l01; dl[1] = l23;
        }
    }
    // ---- stage Q rows for this block: [128 r][64 d] ----
    {
        const int row0 = blockIdx.x * 128;
        const float4* Qg = (const float4*)(Q + ((size_t)b * NN + row0) * DD);
        const int c16 = tid & 15;
#pragma unroll
        for (int it = 0; it < 8; it++) {
            const int r = it * 16 + (tid >> 4);
            float4 v = Qg[r * 16 + c16];
            uint32_t h01, l01, h23, l23;
            split2(v.x, v.y, h01, l01);
            split2(v.z, v.w, h23, l23);
            uint32_t* dh = QH + r * KP_W + c16 * 2;
            uint32_t* dl = QL + r * KP_W + c16 * 2;
            dh[0] = h01; dh[1] = h23;
            dl[0] = l01; dl[1] = l23;
        }
    }
    // ---- stage Vp transposed: VpT[d][j-pairs] (pairs along j for B frags) ----
    {
        const float* Vg = g_Vp + (size_t)b * KK * DD;
        const int c16 = tid & 15;
#pragma unroll
        for (int it = 0; it < 8; it++) {
            const int jp = (tid >> 4) + 16 * it;       // 0..127
            const float* V0 = Vg + (size_t)(2 * jp) * DD;
            const float* V1 = V0 + DD;
#pragma unroll
            for (int r = 0; r < 4; r++) {
                const int d = c16 + 16 * r;
                uint32_t h, lo;
                split2(V0[d], V1[d], h, lo);           // low half = even j
                VTH[d * VT_W + jp] = h;
                VTL[d * VT_W + jp] = lo;
            }
        }
    }
    __syncthreads();

    // ================= Phase 1: scores =================
    float c[32][4];
#pragma unroll
    for (int nt = 0; nt < 32; nt++)
#pragma unroll
        for (int r = 0; r < 4; r++) c[nt][r] = 0.0f;

    const int rowA = 16 * w + g;   // this thread's first row within block
#pragma unroll
    for (int kt = 0; kt < 4; kt++) {
        const int ao = rowA * KP_W + 8 * kt + q4;
        const uint32_t ah0 = QH[ao],               ah1 = QH[ao + 8 * KP_W];
        const uint32_t ah2 = QH[ao + 4],           ah3 = QH[ao + 8 * KP_W + 4];
        const uint32_t al0 = QL[ao],               al1 = QL[ao + 8 * KP_W];
        const uint32_t al2 = QL[ao + 4],           al3 = QL[ao + 8 * KP_W + 4];
#pragma unroll
        for (int nt = 0; nt < 32; nt++) {
            const int bo = (8 * nt + g) * KP_W + 8 * kt + q4;
            const uint32_t bh0 = KPH[bo], bh1 = KPH[bo + 4];
            const uint32_t bl0 = KPL[bo], bl1 = KPL[bo + 4];
            mma_bf16(c[nt], ah0, ah1, ah2, ah3, bh0, bh1);
            mma_bf16(c[nt], ah0, ah1, ah2, ah3, bl0, bl1);
            mma_bf16(c[nt], al0, al1, al2, al3, bh0, bh1);
        }
    }

    // ================= softmax (rows rowA, rowA+8) =================
    float m0 = -1e30f, m1 = -1e30f;
#pragma unroll
    for (int nt = 0; nt < 32; nt++) {
        m0 = fmaxf(m0, fmaxf(c[nt][0], c[nt][1]));
        m1 = fmaxf(m1, fmaxf(c[nt][2], c[nt][3]));
    }
    m0 = fmaxf(m0, __shfl_xor_sync(0xffffffffu, m0, 1));
    m0 = fmaxf(m0, __shfl_xor_sync(0xffffffffu, m0, 2));
    m1 = fmaxf(m1, __shfl_xor_sync(0xffffffffu, m1, 1));
    m1 = fmaxf(m1, __shfl_xor_sync(0xffffffffu, m1, 2));
    const float m0s = m0 * 0.125f, m1s = m1 * 0.125f;

    uint32_t PH0[32], PL0[32], PH1[32], PL1[32];
    float s0 = 0.0f, s1 = 0.0f;
#pragma unroll
    for (int nt = 0; nt < 32; nt++) {
        float e0 = __expf(fmaf(c[nt][0], 0.125f, -m0s));
        float e1 = __expf(fmaf(c[nt][1], 0.125f, -m0s));
        float e2 = __expf(fmaf(c[nt][2], 0.125f, -m1s));
        float e3 = __expf(fmaf(c[nt][3], 0.125f, -m1s));
        s0 += e0 + e1;
        s1 += e2 + e3;
        split2(e0, e1, PH0[nt], PL0[nt]);
        split2(e2, e3, PH1[nt], PL1[nt]);
    }
    s0 += __shfl_xor_sync(0xffffffffu, s0, 1);
    s0 += __shfl_xor_sync(0xffffffffu, s0, 2);
    s1 += __shfl_xor_sync(0xffffffffu, s1, 1);
    s1 += __shfl_xor_sync(0xffffffffu, s1, 2);
    const float inv0 = 1.0f / s0, inv1 = 1.0f / s1;

    // ================= Phase 2: O = P * Vp =================
    float o[8][4];
#pragma unroll
    for (int nt = 0; nt < 8; nt++)
#pragma unroll
        for (int r = 0; r < 4; r++) o[nt][r] = 0.0f;

#pragma unroll
    for (int kt = 0; kt < 16; kt++) {
        const uint32_t ah0 = PH0[2 * kt],     ah1 = PH1[2 * kt];
        const uint32_t ah2 = PH0[2 * kt + 1], ah3 = PH1[2 * kt + 1];
        const uint32_t al0 = PL0[2 * kt],     al1 = PL1[2 * kt];
        const uint32_t al2 = PL0[2 * kt + 1], al3 = PL1[2 * kt + 1];
#pragma unroll
        for (int nt = 0; nt < 8; nt++) {
            const int bo = (8 * nt + g) * VT_W + 8 * kt + q4;
            const uint32_t bh0 = VTH[bo], bh1 = VTH[bo + 4];
            const uint32_t bl0 = VTL[bo], bl1 = VTL[bo + 4];
            mma_bf16(o[nt], ah0, ah1, ah2, ah3, bh0, bh1);
            mma_bf16(o[nt], ah0, ah1, ah2, ah3, bl0, bl1);
            mma_bf16(o[nt], al0, al1, al2, al3, bh0, bh1);
        }
    }

    // ---- epilogue ----
    const int grow = blockIdx.x * 128 + rowA;
    float* O0 = out + ((size_t)b * NN + grow) * DD;
    float* O1 = O0 + 8 * DD;
#pragma unroll
    for (int nt = 0; nt < 8; nt++) {
        const int d = 8 * nt + 2 * q4;
        *(float2*)(O0 + d) = make_float2(o[nt][0] * inv0, o[nt][1] * inv0);
        *(float2*)(O1 + d) = make_float2(o[nt][2] * inv1, o[nt][3] * inv1);
    }
}

// ---------------------------------------------------------------------------
extern "C" void kernel_launch(void* const* d_in, const int* in_sizes, int n_in,
                              void* d_out, int out_size) {
    const float* Q = (const float*)d_in[0];
    const float* K = (const float*)d_in[1];
    const float* V = (const float*)d_in[2];
    const float* E = (const float*)d_in[3];
    const float* F = (const float*)d_in[4];
    float* out = (float*)d_out;

    static bool attr_set = false;
    const int attn_smem = ATTN_WORDS * 4;                                   // 178176 B
    const int proj_smem = (2 * 128 * AST + 2 * 64 * AST) * sizeof(float);   // 55296 B
    if (!attr_set) {
        cudaFuncSetAttribute(attn_kernel, cudaFuncAttributeMaxDynamicSharedMemorySize, attn_smem);
        cudaFuncSetAttribute(proj_mma_kernel, cudaFuncAttributeMaxDynamicSharedMemorySize, proj_smem);
        attr_set = true;
    }

    proj_mma_kernel<<<dim3(2, BB, 2), 256, proj_smem>>>(K, V, E, F);
    attn_kernel<<<dim3(NN / 128, BB), 256, attn_smem>>>(Q, out);
}

// round 10
// speedup vs baseline: 4.1547x; 2.0800x over previous
#include <cuda_runtime.h>
#include <cuda_bf16.h>
#include <cstdint>

#define BB 32
#define NN 4096
#define DD 64
#define KK 256

// Scratch: projections [b][j][d]
__device__ __align__(16) float g_Kp[BB * KK * DD];
__device__ __align__(16) float g_Vp[BB * KK * DD];

// mma.sync m16n8k16 bf16: D += A*B (a,b are packed bf16x2 regs)
__device__ __forceinline__ void mma_bf16(float c[4], uint32_t a0, uint32_t a1,
                                         uint32_t a2, uint32_t a3,
                                         uint32_t b0, uint32_t b1) {
    asm volatile(
        "mma.sync.aligned.m16n8k16.row.col.f32.bf16.bf16.f32 "
        "{%0, %1, %2, %3}, {%4, %5, %6, %7}, {%8, %9}, {%0, %1, %2, %3};"
        : "+f"(c[0]), "+f"(c[1]), "+f"(c[2]), "+f"(c[3])
        : "r"(a0), "r"(a1), "r"(a2), "r"(a3), "r"(b0), "r"(b1));
}

// pack two floats to bf16x2: lo -> bits[15:0], hi -> bits[31:16]
__device__ __forceinline__ uint32_t pack_bf16x2(float lo, float hi) {
    uint32_t r;
    asm("cvt.rn.bf16x2.f32 %0, %1, %2;" : "=r"(r) : "f"(hi), "f"(lo));
    return r;
}
__device__ __forceinline__ float bf16lo_f(uint32_t p) { return __uint_as_float(p << 16); }
__device__ __forceinline__ float bf16hi_f(uint32_t p) { return __uint_as_float(p & 0xffff0000u); }

// split (x0,x1) into hi/lo bf16x2 pairs
__device__ __forceinline__ void split2(float x0, float x1, uint32_t& h, uint32_t& lo) {
    h  = pack_bf16x2(x0, x1);
    lo = pack_bf16x2(x0 - bf16lo_f(h), x1 - bf16hi_f(h));
}

// ---------------------------------------------------------------------------
// Kernel A: proj via mma.sync bf16 m16n8k16 (3-term hi/lo compensated),
// software pipelined over register ping-pong.
//   C[j, d] = sum_n W[n][j] * X[b][n][d]
// grid (2 jh, 32 b, 2 which), 256 threads (8 warps).
// Block tile [128 j x 64 d]; warp tile [32 j x 32 d]; K chunked by 32.
// Smem rows: 20 uint32 words (16 bf16x2 pairs + 4 pad); 20 % 32 == 4
// -> fragment loads conflict-free (same argument as the attn kernel).
// ---------------------------------------------------------------------------
#define KC   32
#define PST  20
#define PNCH (NN / KC)

__global__ void __launch_bounds__(256, 1)
proj_mma_kernel(const float* __restrict__ Kin, const float* __restrict__ Vin,
                const float* __restrict__ Ein, const float* __restrict__ Fin) {
    extern __shared__ uint32_t psu[];
    uint32_t* Ah = psu;                    // [128][20]
    uint32_t* Al = Ah + 128 * PST;
    uint32_t* Bh = Al + 128 * PST;         // [64][20]
    uint32_t* Bl = Bh + 64 * PST;

    const int jh    = blockIdx.x;
    const int b     = blockIdx.y;
    const int which = blockIdx.z;
    const float* __restrict__ X = which ? Vin : Kin;   // [B][N][64]
    const float* __restrict__ W = which ? Fin : Ein;   // [N][256]
    float* __restrict__ P = which ? g_Vp : g_Kp;
    const int j0 = jh * 128;

    const int tid = threadIdx.x;
    const int wid = tid >> 5;
    const int l   = tid & 31;
    const int g   = l >> 2;
    const int q4  = l & 3;
    const int wj  = wid & 3;     // j quarter (32 rows)
    const int wd  = wid >> 2;    // d half (32 cols)

    // staging maps
    const int jA = tid & 127, gA = tid >> 7;   // A: 128 j-lanes, 2 n-groups of 16
    const int dB = tid & 63,  gB = tid >> 6;   // B: 64 d-lanes, 4 n-groups of 8

    float c[2][4][4];
#pragma unroll
    for (int mt = 0; mt < 2; mt++)
#pragma unroll
        for (int nt = 0; nt < 4; nt++)
#pragma unroll
            for (int r = 0; r < 4; r++) c[mt][nt][r] = 0.0f;

    auto loadA = [&](float* r, int cc) {
#pragma unroll
        for (int grp = 0; grp < 4; grp++) {
            const int n = gA * 16 + grp * 4;
            const float* Wp = W + (size_t)(cc * KC + n) * KK + j0 + jA;
            r[grp * 4 + 0] = Wp[0];
            r[grp * 4 + 1] = Wp[KK];
            r[grp * 4 + 2] = Wp[2 * KK];
            r[grp * 4 + 3] = Wp[3 * KK];
        }
    };
    auto loadB = [&](float* r, int cc) {
#pragma unroll
        for (int grp = 0; grp < 2; grp++) {
            const int n = gB * 8 + grp * 4;
            const float* Xp = X + ((size_t)b * NN + cc * KC + n) * DD + dB;
            r[grp * 4 + 0] = Xp[0];
            r[grp * 4 + 1] = Xp[DD];
            r[grp * 4 + 2] = Xp[2 * DD];
            r[grp * 4 + 3] = Xp[3 * DD];
        }
    };
    auto stage = [&](const float* ra, const float* rb) {
#pragma unroll
        for (int grp = 0; grp < 4; grp++) {
            const int pr = gA * 8 + grp * 2;          // pair index = n/2
            uint32_t h0, l0, h1, l1;
            split2(ra[grp * 4 + 0], ra[grp * 4 + 1], h0, l0);
            split2(ra[grp * 4 + 2], ra[grp * 4 + 3], h1, l1);
            *(uint2*)(Ah + jA * PST + pr) = make_uint2(h0, h1);
            *(uint2*)(Al + jA * PST + pr) = make_uint2(l0, l1);
        }
#pragma unroll
        for (int grp = 0; grp < 2; grp++) {
            const int pr = gB * 4 + grp * 2;
            uint32_t h0, l0, h1, l1;
            split2(rb[grp * 4 + 0], rb[grp * 4 + 1], h0, l0);
            split2(rb[grp * 4 + 2], rb[grp * 4 + 3], h1, l1);
            *(uint2*)(Bh + dB * PST + pr) = make_uint2(h0, h1);
            *(uint2*)(Bl + dB * PST + pr) = make_uint2(l0, l1);
        }
    };
    auto mmaChunk = [&]() {
#pragma unroll
        for (int ks = 0; ks < 2; ks++) {
            const int pb = ks * 8;

            uint32_t ah[2][4], al[2][4];
#pragma unroll
            for (int mt = 0; mt < 2; mt++) {
                const int ao = (wj * 32 + mt * 16 + g) * PST + pb + q4;
                ah[mt][0] = Ah[ao];
                ah[mt][1] = Ah[ao + 8 * PST];
                ah[mt][2] = Ah[ao + 4];
                ah[mt][3] = Ah[ao + 8 * PST + 4];
                al[mt][0] = Al[ao];
                al[mt][1] = Al[ao + 8 * PST];
                al[mt][2] = Al[ao + 4];
                al[mt][3] = Al[ao + 8 * PST + 4];
            }
            uint32_t bh[4][2], bl[4][2];
#pragma unroll
            for (int nt = 0; nt < 4; nt++) {
                const int bo = (wd * 32 + nt * 8 + g) * PST + pb + q4;
                bh[nt][0] = Bh[bo];
                bh[nt][1] = Bh[bo + 4];
                bl[nt][0] = Bl[bo];
                bl[nt][1] = Bl[bo + 4];
            }
#pragma unroll
            for (int mt = 0; mt < 2; mt++)
#pragma unroll
                for (int nt = 0; nt < 4; nt++) {
                    mma_bf16(c[mt][nt], ah[mt][0], ah[mt][1], ah[mt][2], ah[mt][3],
                             bh[nt][0], bh[nt][1]);
                    mma_bf16(c[mt][nt], ah[mt][0], ah[mt][1], ah[mt][2], ah[mt][3],
                             bl[nt][0], bl[nt][1]);
                    mma_bf16(c[mt][nt], al[mt][0], al[mt][1], al[mt][2], al[mt][3],
                             bh[nt][0], bh[nt][1]);
                }
        }
    };

    // ---- pipelined main loop (PNCH = 128, even) ----
    float rA0[16], rB0[8], rA1[16], rB1[8];
    loadA(rA0, 0);
    loadB(rB0, 0);

    for (int cc = 0; cc < PNCH; cc += 2) {
        stage(rA0, rB0);
        __syncthreads();
        if (cc + 1 < PNCH) { loadA(rA1, cc + 1); loadB(rB1, cc + 1); }
        mmaChunk();
        __syncthreads();

        stage(rA1, rB1);
        __syncthreads();
        if (cc + 2 < PNCH) { loadA(rA0, cc + 2); loadB(rB0, cc + 2); }
        mmaChunk();
        __syncthreads();
    }

    // ---- epilogue: C fragments -> P[b][j][d] ----
#pragma unroll
    for (int mt = 0; mt < 2; mt++) {
        const int row = j0 + wj * 32 + mt * 16 + g;
        float* p = P + ((size_t)b * KK + row) * DD;
#pragma unroll
        for (int nt = 0; nt < 4; nt++) {
            const int col = wd * 32 + nt * 8 + q4 * 2;
            *(float2*)(p + col)          = make_float2(c[mt][nt][0], c[mt][nt][1]);
            *(float2*)(p + 8 * DD + col) = make_float2(c[mt][nt][2], c[mt][nt][3]);
        }
    }
}

// ---------------------------------------------------------------------------
// Kernel B: fully tensorized flash-style attention, bf16x3 mma.sync.
// (unchanged from R9 passing version)
// ---------------------------------------------------------------------------
#define KP_W 36    // words per Kp/Q row (72 bf16)
#define VT_W 132   // words per VpT row (264 bf16)

#define OFF_KPH 0
#define OFF_KPL (OFF_KPH + 256 * KP_W)
#define OFF_VTH (OFF_KPL + 256 * KP_W)
#define OFF_VTL (OFF_VTH + 64 * VT_W)
#define OFF_QH  (OFF_VTL + 64 * VT_W)
#define OFF_QL  (OFF_QH + 128 * KP_W)
#define ATTN_WORDS (OFF_QL + 128 * KP_W)

__global__ void __launch_bounds__(256, 1)
attn_kernel(const float* __restrict__ Q, float* __restrict__ out) {
    extern __shared__ uint32_t asm_w[];
    uint32_t* KPH = asm_w + OFF_KPH;
    uint32_t* KPL = asm_w + OFF_KPL;
    uint32_t* VTH = asm_w + OFF_VTH;
    uint32_t* VTL = asm_w + OFF_VTL;
    uint32_t* QH  = asm_w + OFF_QH;
    uint32_t* QL  = asm_w + OFF_QL;

    const int b   = blockIdx.y;
    const int tid = threadIdx.x;
    const int w   = tid >> 5;
    const int l   = tid & 31;
    const int g   = l >> 2;
    const int q4  = l & 3;

    // ---- stage Kp: [256 j][64 d] fp32 -> bf16 hi/lo pairs along d ----
    {
        const float4* Kg = (const float4*)(g_Kp + (size_t)b * KK * DD);
        const int c16 = tid & 15;
#pragma unroll
        for (int it = 0; it < 16; it++) {
            const int j = it * 16 + (tid >> 4);
            float4 v = Kg[j * 16 + c16];
            uint32_t h01, l01, h23, l23;
            split2(v.x, v.y, h01, l01);
            split2(v.z, v.w, h23, l23);
            uint32_t* dh = KPH + j * KP_W + c16 * 2;
            uint32_t* dl = KPL + j * KP_W + c16 * 2;
            dh[0] = h01; dh[1] = h23;
            dl[0] = l01; dl[1] = l23;
        }
    }
    // ---- stage Q rows for this block: [128 r][64 d] ----
    {
        const int row0 = blockIdx.x * 128;
        const float4* Qg = (const float4*)(Q + ((size_t)b * NN + row0) * DD);
        const int c16 = tid & 15;
#pragma unroll
        for (int it = 0; it < 8; it++) {
            const int r = it * 16 + (tid >> 4);
            float4 v = Qg[r * 16 + c16];
            uint32_t h01, l01, h23, l23;
            split2(v.x, v.y, h01, l01);
            split2(v.z, v.w, h23, l23);
            uint32_t* dh = QH + r * KP_W + c16 * 2;
            uint32_t* dl = QL + r * KP_W + c16 * 2;
            dh[0] = h01; dh[1] = h23;
            dl[0] = l01; dl[1] = l23;
        }
    }
    // ---- stage Vp transposed: VpT[d][j-pairs] ----
    {
        const float* Vg = g_Vp + (size_t)b * KK * DD;
        const int c16 = tid & 15;
#pragma unroll
        for (int it = 0; it < 8; it++) {
            const int jp = (tid >> 4) + 16 * it;       // 0..127
            const float* V0 = Vg + (size_t)(2 * jp) * DD;
            const float* V1 = V0 + DD;
#pragma unroll
            for (int r = 0; r < 4; r++) {
                const int d = c16 + 16 * r;
                uint32_t h, lo;
                split2(V0[d], V1[d], h, lo);
                VTH[d * VT_W + jp] = h;
                VTL[d * VT_W + jp] = lo;
            }
        }
    }
    __syncthreads();

    // ================= Phase 1: scores =================
    float c[32][4];
#pragma unroll
    for (int nt = 0; nt < 32; nt++)
#pragma unroll
        for (int r = 0; r < 4; r++) c[nt][r] = 0.0f;

    const int rowA = 16 * w + g;
#pragma unroll
    for (int kt = 0; kt < 4; kt++) {
        const int ao = rowA * KP_W + 8 * kt + q4;
        const uint32_t ah0 = QH[ao],     ah1 = QH[ao + 8 * KP_W];
        const uint32_t ah2 = QH[ao + 4], ah3 = QH[ao + 8 * KP_W + 4];
        const uint32_t al0 = QL[ao],     al1 = QL[ao + 8 * KP_W];
        const uint32_t al2 = QL[ao + 4], al3 = QL[ao + 8 * KP_W + 4];
#pragma unroll
        for (int nt = 0; nt < 32; nt++) {
            const int bo = (8 * nt + g) * KP_W + 8 * kt + q4;
            const uint32_t bh0 = KPH[bo], bh1 = KPH[bo + 4];
            const uint32_t bl0 = KPL[bo], bl1 = KPL[bo + 4];
            mma_bf16(c[nt], ah0, ah1, ah2, ah3, bh0, bh1);
            mma_bf16(c[nt], ah0, ah1, ah2, ah3, bl0, bl1);
            mma_bf16(c[nt], al0, al1, al2, al3, bh0, bh1);
        }
    }

    // ================= softmax (rows rowA, rowA+8) =================
    float m0 = -1e30f, m1 = -1e30f;
#pragma unroll
    for (int nt = 0; nt < 32; nt++) {
        m0 = fmaxf(m0, fmaxf(c[nt][0], c[nt][1]));
        m1 = fmaxf(m1, fmaxf(c[nt][2], c[nt][3]));
    }
    m0 = fmaxf(m0, __shfl_xor_sync(0xffffffffu, m0, 1));
    m0 = fmaxf(m0, __shfl_xor_sync(0xffffffffu, m0, 2));
    m1 = fmaxf(m1, __shfl_xor_sync(0xffffffffu, m1, 1));
    m1 = fmaxf(m1, __shfl_xor_sync(0xffffffffu, m1, 2));
    const float m0s = m0 * 0.125f, m1s = m1 * 0.125f;

    uint32_t PH0[32], PL0[32], PH1[32], PL1[32];
    float s0 = 0.0f, s1 = 0.0f;
#pragma unroll
    for (int nt = 0; nt < 32; nt++) {
        float e0 = __expf(fmaf(c[nt][0], 0.125f, -m0s));
        float e1 = __expf(fmaf(c[nt][1], 0.125f, -m0s));
        float e2 = __expf(fmaf(c[nt][2], 0.125f, -m1s));
        float e3 = __expf(fmaf(c[nt][3], 0.125f, -m1s));
        s0 += e0 + e1;
        s1 += e2 + e3;
        split2(e0, e1, PH0[nt], PL0[nt]);
        split2(e2, e3, PH1[nt], PL1[nt]);
    }
    s0 += __shfl_xor_sync(0xffffffffu, s0, 1);
    s0 += __shfl_xor_sync(0xffffffffu, s0, 2);
    s1 += __shfl_xor_sync(0xffffffffu, s1, 1);
    s1 += __shfl_xor_sync(0xffffffffu, s1, 2);
    const float inv0 = 1.0f / s0, inv1 = 1.0f / s1;

    // ================= Phase 2: O = P * Vp =================
    float o[8][4];
#pragma unroll
    for (int nt = 0; nt < 8; nt++)
#pragma unroll
        for (int r = 0; r < 4; r++) o[nt][r] = 0.0f;

#pragma unroll
    for (int kt = 0; kt < 16; kt++) {
        const uint32_t ah0 = PH0[2 * kt],     ah1 = PH1[2 * kt];
        const uint32_t ah2 = PH0[2 * kt + 1], ah3 = PH1[2 * kt + 1];
        const uint32_t al0 = PL0[2 * kt],     al1 = PL1[2 * kt];
        const uint32_t al2 = PL0[2 * kt + 1], al3 = PL1[2 * kt + 1];
#pragma unroll
        for (int nt = 0; nt < 8; nt++) {
            const int bo = (8 * nt + g) * VT_W + 8 * kt + q4;
            const uint32_t bh0 = VTH[bo], bh1 = VTH[bo + 4];
            const uint32_t bl0 = VTL[bo], bl1 = VTL[bo + 4];
            mma_bf16(o[nt], ah0, ah1, ah2, ah3, bh0, bh1);
            mma_bf16(o[nt], ah0, ah1, ah2, ah3, bl0, bl1);
            mma_bf16(o[nt], al0, al1, al2, al3, bh0, bh1);
        }
    }

    // ---- epilogue ----
    const int grow = blockIdx.x * 128 + rowA;
    float* O0 = out + ((size_t)b * NN + grow) * DD;
    float* O1 = O0 + 8 * DD;
#pragma unroll
    for (int nt = 0; nt < 8; nt++) {
        const int d = 8 * nt + 2 * q4;
        *(float2*)(O0 + d) = make_float2(o[nt][0] * inv0, o[nt][1] * inv0);
        *(float2*)(O1 + d) = make_float2(o[nt][2] * inv1, o[nt][3] * inv1);
    }
}

// ---------------------------------------------------------------------------
extern "C" void kernel_launch(void* const* d_in, const int* in_sizes, int n_in,
                              void* d_out, int out_size) {
    const float* Q = (const float*)d_in[0];
    const float* K = (const float*)d_in[1];
    const float* V = (const float*)d_in[2];
    const float* E = (const float*)d_in[3];
    const float* F = (const float*)d_in[4];
    float* out = (float*)d_out;

    static bool attr_set = false;
    const int attn_smem = ATTN_WORDS * 4;                        // 178176 B
    const int proj_smem = (2 * 128 + 2 * 64) * PST * 4;          // 30720 B
    if (!attr_set) {
        cudaFuncSetAttribute(attn_kernel, cudaFuncAttributeMaxDynamicSharedMemorySize, attn_smem);
        cudaFuncSetAttribute(proj_mma_kernel, cudaFuncAttributeMaxDynamicSharedMemorySize, proj_smem);
        attr_set = true;
    }

    proj_mma_kernel<<<dim3(2, BB, 2), 256, proj_smem>>>(K, V, E, F);
    attn_kernel<<<dim3(NN / 128, BB), 256, attn_smem>>>(Q, out);
}